// round 11
// baseline (speedup 1.0000x reference)
#include <cuda_runtime.h>
#include <math.h>
#include <stdint.h>

#define Bn   8
#define HWn  1024
#define NEGn 256

// ---------------- device scratch ----------------------------------------------
__device__ __align__(16) unsigned g_z1b[Bn * HWn * 32];   // bf16x2 pixel-major, 128B rows
__device__ __align__(16) unsigned g_z2b[Bn * HWn * 32];
__device__ float g_rz1n[Bn * HWn];
__device__ float g_rz2n[Bn * HWn];
__device__ float g_z1sq[Bn * HWn];
__device__ float g_pn [128 * NEGn];
__device__ float g_s0p[128];
__device__ unsigned g_ticket = 0;

__device__ __forceinline__ uint32_t smem_to_u32(const void* p) {
    uint32_t a;
    asm("{ .reg .u64 t; cvta.to.shared.u64 t, %1; cvt.u32.u64 %0, t; }" : "=r"(a) : "l"(p));
    return a;
}
#define SMEM_SWIZZLE_128B(o) ((o) ^ (((o) >> 3) & 0x70))
#define CP_ASYNC16(dst_u32, src) \
    asm volatile("cp.async.cg.shared.global [%0], [%1], 16;" :: "r"(dst_u32), "l"(src))
#define CP_COMMIT() asm volatile("cp.async.commit_group;" ::: "memory")
#define CP_WAIT0()  asm volatile("cp.async.wait_group 0;" ::: "memory")

// round-to-nearest-even fp32 -> bf16-valued fp32
__device__ __forceinline__ float bf16q(float f) {
    unsigned u = __float_as_uint(f);
    u = (u + 0x7FFFu + ((u >> 16) & 1u)) & 0xFFFF0000u;
    return __uint_as_float(u);
}

__device__ __forceinline__ void ldsm_x4(uint32_t& r0, uint32_t& r1, uint32_t& r2,
                                        uint32_t& r3, uint32_t addr) {
    asm volatile("ldmatrix.sync.aligned.m8n8.x4.shared.b16 {%0,%1,%2,%3}, [%4];"
                 : "=r"(r0), "=r"(r1), "=r"(r2), "=r"(r3) : "r"(addr));
}
__device__ __forceinline__ void ldsm_x2(uint32_t& r0, uint32_t& r1, uint32_t addr) {
    asm volatile("ldmatrix.sync.aligned.m8n8.x2.shared.b16 {%0,%1}, [%2];"
                 : "=r"(r0), "=r"(r1) : "r"(addr));
}
__device__ __forceinline__ void mma16816(float* c, const uint32_t* a, const uint32_t* b) {
    asm volatile("mma.sync.aligned.m16n8k16.row.col.f32.bf16.bf16.f32 "
                 "{%0,%1,%2,%3}, {%4,%5,%6,%7}, {%8,%9}, {%0,%1,%2,%3};"
                 : "+f"(c[0]), "+f"(c[1]), "+f"(c[2]), "+f"(c[3])
                 : "r"(a[0]), "r"(a[1]), "r"(a[2]), "r"(a[3]), "r"(b[0]), "r"(b[1]));
}

// ---------------- prep: transpose to bf16 pixel-major + norms ------------------
__global__ void prep_kernel(const float* __restrict__ z1,
                            const float* __restrict__ z2) {
    __shared__ float ts[64][132];
    const int s  = blockIdx.z;
    const int b  = blockIdx.y;
    const int q0 = blockIdx.x * 128;
    const int t  = threadIdx.x;

    const float* zp = s ? z2 : z1;
    #pragma unroll
    for (int it = 0; it < 8; it++) {
        int u = it * 256 + t;
        int c = u >> 5, jq = u & 31;
        float4 v = *(const float4*)(zp + ((b * 64 + c) << 10) + q0 + jq * 4);
        float* d = &ts[c][jq * 4];
        d[0] = bf16q(v.x); d[1] = bf16q(v.y);
        d[2] = bf16q(v.z); d[3] = bf16q(v.w);
    }
    __syncthreads();

    if (t < 128) {
        float sum = 0.f;
        #pragma unroll
        for (int c = 0; c < 64; c++) { float x = ts[c][t]; sum += x * x; }
        int gi = (b << 10) + q0 + t;
        if (s == 0) { g_z1sq[gi] = sum; g_rz1n[gi] = rsqrtf(sum); }
        else        { g_rz2n[gi] = rsqrtf(sum); }
    }

    unsigned* outp = s ? g_z2b : g_z1b;
    #pragma unroll
    for (int it = 0; it < 16; it++) {
        int u = it * 256 + t;
        int px = u & 127, cp = u >> 7;
        unsigned lo = __float_as_uint(ts[2 * cp][px]) >> 16;
        unsigned hi = __float_as_uint(ts[2 * cp + 1][px]) >> 16;
        outp[(((b << 10) + q0 + px) << 5) + cp] = lo | (hi << 16);
    }
}

// ---------------- fused GEMM + gather + final (512 thr, weight-in-MMA) ---------
#define FS_SG    0
#define SG_PITCH 2064
#define FS_SB0   132096
#define FS_SB1   148480
#define FS_SA    164864
#define FS_RZ1   173056
#define FS_RZ2   173312
#define FS_IMG   177408
#define FS_DOT   193792
#define FS_MISC  210176
#define FS_WSM   210688                     // float[64] weights
#define FS_TOTAL 210944

__global__ void __launch_bounds__(512) fused_kernel(
        const int* __restrict__ neg_idx, const float* __restrict__ img,
        float* __restrict__ out, int out_size) {
    extern __shared__ char smem[];
    const uint32_t sb = smem_to_u32(smem);
    const int t = threadIdx.x, w = t >> 5, lane = t & 31;
    const int pt = blockIdx.x, b = blockIdx.y;
    const int wm = w >> 3, wn = w & 7;          // 2x8 warp grid; warp tile 32p x 16q

    float*  rz1s = (float*)(smem + FS_RZ1);
    float*  rz2s = (float*)(smem + FS_RZ2);
    float4* imgs = (float4*)(smem + FS_IMG);
    float*  sdot = (float*)(smem + FS_DOT);
    float*  w_sm = (float*)(smem + FS_WSM);
    float*  s0w  = (float*)(smem + FS_MISC);
    float*  r1s  = (float*)(smem + FS_MISC + 64);
    float*  r2s  = (float*)(smem + FS_MISC + 128);
    float*  lb   = (float*)(smem + FS_MISC + 192);
    float*  s0b  = (float*)(smem + FS_MISC + 224);
    float*  s2b  = (float*)(smem + FS_MISC + 256);
    unsigned* is_last = (unsigned*)(smem + FS_MISC + 288);

    const float INV_EUC   = 1.0f / sqrtf((float)(31 * 31 + 31 * 31));
    const float INV_SQRT3 = 0.57735026919f;
    const int*  negHb = neg_idx + ((size_t)(b * 2) << 18);
    const int*  negWb = negHb + (1 << 18);
    const int   p0 = (pt << 6) + (w << 2);      // warp's first p

    // ---- prolog: A + B0 via cp.async, norms, img table, L2 prefetch ----
    {
        const uint4* srcA = (const uint4*)g_z1b + (((size_t)(b << 10) + (pt << 6)) << 3);
        int row = t >> 3, ub = t & 7;
        CP_ASYNC16(sb + FS_SA + SMEM_SWIZZLE_128B((uint32_t)(row * 128 + ub * 16)),
                   srcA + t);

        const uint4* srcB = (const uint4*)g_z2b + ((size_t)(b << 10) << 3);
        #pragma unroll
        for (int k = 0; k < 2; k++) {
            int u = k * 512 + t;
            int r2 = u >> 3, u2 = u & 7;
            CP_ASYNC16(sb + FS_SB0 + SMEM_SWIZZLE_128B((uint32_t)(r2 * 128 + u2 * 16)),
                       srcB + u);
        }
        CP_COMMIT();

        if (t < 64) rz1s[t] = g_rz1n[(b << 10) + (pt << 6) + t];
        #pragma unroll
        for (int k = 0; k < 2; k++) {
            int i = k * 512 + t;
            rz2s[i] = g_rz2n[(b << 10) + i];
            imgs[i] = make_float4(img[i], img[HWn + i], img[2 * HWn + i], 0.f);
        }
        // L2-prefetch this block's neg_idx slice
        const char* nh = (const char*)(negHb + ((pt << 6) << 8));
        asm volatile("prefetch.global.L2 [%0];" :: "l"(nh + t * 128));
        asm volatile("prefetch.global.L2 [%0];" :: "l"(nh + (1 << 20) + t * 128));
        CP_WAIT0();
    }
    __syncthreads();

    // ---- hoist A fragments ----
    uint32_t af[4][2][4];
    #pragma unroll
    for (int ks = 0; ks < 4; ks++)
        #pragma unroll
        for (int mi = 0; mi < 2; mi++) {
            int row  = (wm << 5) + (mi << 4) + (lane & 15);
            int half = lane >> 4;
            uint32_t off = SMEM_SWIZZLE_128B((uint32_t)(row * 128 + ks * 32 + half * 16));
            ldsm_x4(af[ks][mi][0], af[ks][mi][1], af[ks][mi][2], af[ks][mi][3],
                    sb + FS_SA + off);
        }

    float sim0acc = 0.f;

    // ---- MMA mainloop over 8 q-tiles; weight compute interleaved on even qt ----
    #pragma unroll 1
    for (int qt = 0; qt < 8; qt++) {
        const int cur = qt & 1;
        const uint32_t sbB = sb + (cur ? FS_SB1 : FS_SB0);

        if (qt < 7) {
            const uint32_t dstB = sb + ((cur ^ 1) ? FS_SB1 : FS_SB0);
            const uint4* srcB = (const uint4*)g_z2b +
                                (((size_t)(b << 10) + ((qt + 1) << 7)) << 3);
            #pragma unroll
            for (int k = 0; k < 2; k++) {
                int u = k * 512 + t;
                int r2 = u >> 3, u2 = u & 7;
                CP_ASYNC16(dstB + SMEM_SWIZZLE_128B((uint32_t)(r2 * 128 + u2 * 16)),
                           srcB + u);
            }
        }
        CP_COMMIT();

        // issue idx loads early on even qt (latency hidden by MMA below)
        int qv[8];
        if ((qt & 1) == 0) {
            const int p = p0 + (qt >> 1);
            const int* nH = negHb + (p << 8);
            const int* nW = negWb + (p << 8);
            #pragma unroll
            for (int r = 0; r < 8; r++) {
                int n = (r << 5) + lane;
                qv[r] = (nH[n] << 5) + nW[n];
            }
        }

        float c[2][2][4];
        #pragma unroll
        for (int mi = 0; mi < 2; mi++)
            #pragma unroll
            for (int ni = 0; ni < 2; ni++)
                #pragma unroll
                for (int r = 0; r < 4; r++) c[mi][ni][r] = 0.f;

        #pragma unroll
        for (int ks = 0; ks < 4; ks++) {
            uint32_t bb[2][2];
            #pragma unroll
            for (int ni = 0; ni < 2; ni++) {
                int row  = (wn << 4) + (ni << 3) + (lane & 7);
                int half = (lane >> 3) & 1;
                uint32_t off = SMEM_SWIZZLE_128B((uint32_t)(row * 128 + ks * 32 + half * 16));
                ldsm_x2(bb[ni][0], bb[ni][1], sbB + off);
            }
            #pragma unroll
            for (int mi = 0; mi < 2; mi++)
                #pragma unroll
                for (int ni = 0; ni < 2; ni++)
                    mma16816(c[mi][ni], af[ks][mi], bb[ni]);
        }

        // epilogue: scale -> bf16x2 -> STS into SG
        #pragma unroll
        for (int mi = 0; mi < 2; mi++) {
            int r0 = (wm << 5) + (mi << 4) + (lane >> 2);
            int r1 = r0 + 8;
            float z1a = rz1s[r0], z1b = rz1s[r1];
            #pragma unroll
            for (int ni = 0; ni < 2; ni++) {
                int cq = (wn << 4) + (ni << 3) + ((lane & 3) << 1);
                int gq = (qt << 7) + cq;
                float rq0 = rz2s[gq], rq1 = rz2s[gq + 1];
                uint32_t u0, u1;
                float a0 = c[mi][ni][0] * z1a * rq0, a1 = c[mi][ni][1] * z1a * rq1;
                float b0 = c[mi][ni][2] * z1b * rq0, b1 = c[mi][ni][3] * z1b * rq1;
                asm("cvt.rn.bf16x2.f32 %0, %1, %2;" : "=r"(u0) : "f"(a1), "f"(a0));
                asm("cvt.rn.bf16x2.f32 %0, %1, %2;" : "=r"(u1) : "f"(b1), "f"(b0));
                *(uint32_t*)(smem + FS_SG + r0 * SG_PITCH + gq * 2) = u0;
                *(uint32_t*)(smem + FS_SG + r1 * SG_PITCH + gq * 2) = u1;
            }
        }

        // weight compute for p#(qt/2) — fills cp.async wait shadow
        if ((qt & 1) == 0) {
            const int pl = (w << 2) + (qt >> 1);
            const int p  = (pt << 6) + pl;
            const float hp = (float)(p >> 5), wp = (float)(p & 31);
            const float4 ctr = imgs[p];
            float eucsq = 0.f, rgbsq = 0.f;
            #pragma unroll
            for (int r = 0; r < 8; r++) {
                int q  = qv[r];
                int nh = q >> 5, nw = q & 31;
                float dh = hp - (float)nh, dw = wp - (float)nw;
                eucsq += dh * dh; eucsq += dw * dw;
                float4 c4 = imgs[q];
                float dr = ctr.x - c4.x, dg = ctr.y - c4.y, db = ctr.z - c4.z;
                rgbsq += dr * dr; rgbsq += dg * dg; rgbsq += db * db;
            }
            #pragma unroll
            for (int s = 16; s > 0; s >>= 1) {
                eucsq += __shfl_xor_sync(0xffffffffu, eucsq, s);
                rgbsq += __shfl_xor_sync(0xffffffffu, rgbsq, s);
            }
            if (lane == 0) {
                w_sm[pl] = 0.8f * sqrtf(eucsq) * INV_EUC
                         + 0.2f * sqrtf(rgbsq) * INV_SQRT3;
                float z1sqp = g_z1sq[(b << 10) + p];
                float c0 = z1sqp / fmaxf(z1sqp, 1e-8f);
                sim0acc += fminf(fabsf(c0), 1.0f);
            }
        }

        CP_WAIT0();
        __syncthreads();
    }

    // ---- gather phase: pipelined idx reload (L2-hot) + smem G-gather ----
    float acc[8];
    #pragma unroll
    for (int r = 0; r < 8; r++) acc[r] = 0.f;

    int qx[8];
    {
        const int* nH = negHb + (p0 << 8);
        const int* nW = negWb + (p0 << 8);
        #pragma unroll
        for (int r = 0; r < 8; r++) {
            int n = (r << 5) + lane;
            qx[r] = (nH[n] << 5) + nW[n];
        }
    }

    #pragma unroll
    for (int it = 0; it < 4; it++) {
        int qc[8];
        #pragma unroll
        for (int r = 0; r < 8; r++) qc[r] = qx[r];

        if (it < 3) {
            const int* nH = negHb + ((p0 + it + 1) << 8);
            const int* nW = negWb + ((p0 + it + 1) << 8);
            #pragma unroll
            for (int r = 0; r < 8; r++) {
                int n = (r << 5) + lane;
                qx[r] = (nH[n] << 5) + nW[n];
            }
        }

        const int pl = (w << 2) + it;
        const float weight = w_sm[pl];
        const unsigned short* grow = (const unsigned short*)(smem + FS_SG + pl * SG_PITCH);
        #pragma unroll
        for (int r = 0; r < 8; r++) {
            float cosv = __uint_as_float((unsigned)grow[qc[r]] << 16);
            acc[r] += fminf(fabsf(cosv * weight), 1.0f);
        }
    }

    #pragma unroll
    for (int r = 0; r < 8; r++) sdot[w * 256 + (r << 5) + lane] = acc[r];
    if (lane == 0) s0w[w] = sim0acc;
    __syncthreads();

    if (t < NEGn) {
        float s = 0.f;
        #pragma unroll
        for (int k = 0; k < 16; k++) s += sdot[k * 256 + t];
        g_pn[(((b << 4) + pt) << 8) + t] = s;
    }
    if (t == 0) {
        float s = 0.f;
        #pragma unroll
        for (int k = 0; k < 16; k++) s += s0w[k];
        g_s0p[(b << 4) + pt] = s;
    }

    // ---- last-block final reduction: fence on ONE thread only ----
    __syncthreads();
    if (t == 0) {
        __threadfence();
        *is_last = (atomicAdd(&g_ticket, 1u) == 127u);
    }
    __syncthreads();
    if (!*is_last) return;
    if (t == 0) {
        __threadfence();
        g_ticket = 0;
    }
    __syncthreads();

    {
        const int fb = t >> 6;
        const int j  = t & 63;

        float v1 = 0.f, v2 = 0.f;
        #pragma unroll
        for (int h = 0; h < 4; h++) {
            int n = j + (h << 6);
            float s = 0.f;
            #pragma unroll
            for (int k = 0; k < 16; k++)
                s += __ldcg(&g_pn[(((fb << 4) + k) << 8) + n]);
            float sn = s * (0.5f / 1024.0f);
            v2 += sn;
            v1 += fmaxf(log1pf(-sn), -100.0f);
        }
        #pragma unroll
        for (int s = 16; s > 0; s >>= 1) {
            v1 += __shfl_xor_sync(0xffffffffu, v1, s);
            v2 += __shfl_xor_sync(0xffffffffu, v2, s);
        }
        if (lane == 0) { r1s[w] = v1; r2s[w] = v2; }
        __syncthreads();

        if (t < 8) {
            float s1 = r1s[2 * t] + r1s[2 * t + 1];
            float s2 = r2s[2 * t] + r2s[2 * t + 1];
            float s0s = 0.f;
            #pragma unroll
            for (int k = 0; k < 16; k++) s0s += __ldcg(&g_s0p[(t << 4) + k]);
            float s0   = s0s * (1.0f / 1024.0f);
            float logp = fmaxf(logf(s0), -100.0f);
            lb[t]  = -(logp + s1) * (1.0f / 257.0f);
            s0b[t] = s0;
            s2b[t] = s2;
        }
        __syncthreads();

        if (t == 0) {
            float loss = 0.f, o1 = 0.f, o2 = 0.f;
            #pragma unroll
            for (int i = 0; i < 8; i++) { loss += lb[i]; o1 += s0b[i]; o2 += s2b[i]; }
            if (out_size > 0) out[0] = loss * 0.125f;
            if (out_size > 1) out[1] = o1 * 0.125f;
            if (out_size > 2) out[2] = o2 * (2.0f / (256.0f * 8.0f));
        }
    }
}

// ---------------- launch --------------------------------------------------------
extern "C" void kernel_launch(void* const* d_in, const int* in_sizes, int n_in,
                              void* d_out, int out_size) {
    const float* v1   = (const float*)d_in[0];
    const float* v2   = (const float*)d_in[1];
    const float* img  = (const float*)d_in[2];
    const int*   nidx = (const int*)  d_in[3];

    cudaFuncSetAttribute(fused_kernel, cudaFuncAttributeMaxDynamicSharedMemorySize,
                         FS_TOTAL);

    prep_kernel<<<dim3(8, 8, 2), 256>>>(v1, v2);
    fused_kernel<<<dim3(16, 8), 512, FS_TOTAL>>>(nidx, img, (float*)d_out, out_size);
}

// round 12
// speedup vs baseline: 1.1635x; 1.1635x over previous
#include <cuda_runtime.h>
#include <math.h>
#include <stdint.h>

#define Bn   8
#define HWn  1024
#define NEGn 256

// ---------------- device scratch ----------------------------------------------
__device__ __align__(16) unsigned g_z1b[Bn * HWn * 32];   // bf16x2 pixel-major, 128B rows
__device__ __align__(16) unsigned g_z2b[Bn * HWn * 32];
__device__ float g_rz1n[Bn * HWn];
__device__ float g_rz2n[Bn * HWn];
__device__ float g_z1sq[Bn * HWn];
__device__ float g_pn [128 * NEGn];
__device__ float g_s0p[128];
__device__ unsigned g_ticket = 0;

__device__ __forceinline__ uint32_t smem_to_u32(const void* p) {
    uint32_t a;
    asm("{ .reg .u64 t; cvta.to.shared.u64 t, %1; cvt.u32.u64 %0, t; }" : "=r"(a) : "l"(p));
    return a;
}
#define SMEM_SWIZZLE_128B(o) ((o) ^ (((o) >> 3) & 0x70))
#define CP_ASYNC16(dst_u32, src) \
    asm volatile("cp.async.cg.shared.global [%0], [%1], 16;" :: "r"(dst_u32), "l"(src))
#define CP_COMMIT() asm volatile("cp.async.commit_group;" ::: "memory")
#define CP_WAIT0()  asm volatile("cp.async.wait_group 0;" ::: "memory")

// round-to-nearest-even fp32 -> bf16-valued fp32
__device__ __forceinline__ float bf16q(float f) {
    unsigned u = __float_as_uint(f);
    u = (u + 0x7FFFu + ((u >> 16) & 1u)) & 0xFFFF0000u;
    return __uint_as_float(u);
}

__device__ __forceinline__ void ldsm_x4(uint32_t& r0, uint32_t& r1, uint32_t& r2,
                                        uint32_t& r3, uint32_t addr) {
    asm volatile("ldmatrix.sync.aligned.m8n8.x4.shared.b16 {%0,%1,%2,%3}, [%4];"
                 : "=r"(r0), "=r"(r1), "=r"(r2), "=r"(r3) : "r"(addr));
}
__device__ __forceinline__ void ldsm_x2(uint32_t& r0, uint32_t& r1, uint32_t addr) {
    asm volatile("ldmatrix.sync.aligned.m8n8.x2.shared.b16 {%0,%1}, [%2];"
                 : "=r"(r0), "=r"(r1) : "r"(addr));
}
__device__ __forceinline__ void mma16816(float* c, const uint32_t* a, const uint32_t* b) {
    asm volatile("mma.sync.aligned.m16n8k16.row.col.f32.bf16.bf16.f32 "
                 "{%0,%1,%2,%3}, {%4,%5,%6,%7}, {%8,%9}, {%0,%1,%2,%3};"
                 : "+f"(c[0]), "+f"(c[1]), "+f"(c[2]), "+f"(c[3])
                 : "r"(a[0]), "r"(a[1]), "r"(a[2]), "r"(a[3]), "r"(b[0]), "r"(b[1]));
}

// ---------------- prep: transpose to bf16 pixel-major + norms ------------------
__global__ void prep_kernel(const float* __restrict__ z1,
                            const float* __restrict__ z2) {
    __shared__ float ts[64][132];
    const int s  = blockIdx.z;
    const int b  = blockIdx.y;
    const int q0 = blockIdx.x * 128;
    const int t  = threadIdx.x;

    const float* zp = s ? z2 : z1;
    #pragma unroll
    for (int it = 0; it < 8; it++) {
        int u = it * 256 + t;
        int c = u >> 5, jq = u & 31;
        float4 v = *(const float4*)(zp + ((b * 64 + c) << 10) + q0 + jq * 4);
        float* d = &ts[c][jq * 4];
        d[0] = bf16q(v.x); d[1] = bf16q(v.y);
        d[2] = bf16q(v.z); d[3] = bf16q(v.w);
    }
    __syncthreads();

    if (t < 128) {
        float sum = 0.f;
        #pragma unroll
        for (int c = 0; c < 64; c++) { float x = ts[c][t]; sum += x * x; }
        int gi = (b << 10) + q0 + t;
        if (s == 0) { g_z1sq[gi] = sum; g_rz1n[gi] = rsqrtf(sum); }
        else        { g_rz2n[gi] = rsqrtf(sum); }
    }

    unsigned* outp = s ? g_z2b : g_z1b;
    #pragma unroll
    for (int it = 0; it < 16; it++) {
        int u = it * 256 + t;
        int px = u & 127, cp = u >> 7;
        unsigned lo = __float_as_uint(ts[2 * cp][px]) >> 16;
        unsigned hi = __float_as_uint(ts[2 * cp + 1][px]) >> 16;
        outp[(((b << 10) + q0 + px) << 5) + cp] = lo | (hi << 16);
    }
}

// ---------------- fused GEMM + gather + final (R9 shape + int4 idx loads) ------
#define FS_SG    0
#define SG_PITCH 2064
#define FS_SB0   132096
#define FS_SB1   148480
#define FS_SA    164864
#define FS_RZ1   173056
#define FS_RZ2   173312
#define FS_IMG   177408
#define FS_DOT   193792
#define FS_MISC  210176
#define FS_TOTAL 210688

__global__ void __launch_bounds__(512) fused_kernel(
        const int* __restrict__ neg_idx, const float* __restrict__ img,
        float* __restrict__ out, int out_size) {
    extern __shared__ char smem[];
    const uint32_t sb = smem_to_u32(smem);
    const int t = threadIdx.x, w = t >> 5, lane = t & 31;
    const int pt = blockIdx.x, b = blockIdx.y;
    const int wm = w >> 3, wn = w & 7;

    float*  rz1s = (float*)(smem + FS_RZ1);
    float*  rz2s = (float*)(smem + FS_RZ2);
    float4* imgs = (float4*)(smem + FS_IMG);
    float*  sdot = (float*)(smem + FS_DOT);
    float*  s0w  = (float*)(smem + FS_MISC);
    float*  r1s  = (float*)(smem + FS_MISC + 64);
    float*  r2s  = (float*)(smem + FS_MISC + 128);
    float*  lb   = (float*)(smem + FS_MISC + 192);
    float*  s0b  = (float*)(smem + FS_MISC + 224);
    float*  s2b  = (float*)(smem + FS_MISC + 256);
    unsigned* is_last = (unsigned*)(smem + FS_MISC + 288);

    // ---- prolog: A + B0 via cp.async, norms, img table, L2 prefetch ----
    {
        const uint4* srcA = (const uint4*)g_z1b + (((size_t)(b << 10) + (pt << 6)) << 3);
        int row = t >> 3, ub = t & 7;
        CP_ASYNC16(sb + FS_SA + SMEM_SWIZZLE_128B((uint32_t)(row * 128 + ub * 16)),
                   srcA + t);

        const uint4* srcB = (const uint4*)g_z2b + ((size_t)(b << 10) << 3);
        #pragma unroll
        for (int k = 0; k < 2; k++) {
            int u = k * 512 + t;
            int r2 = u >> 3, u2 = u & 7;
            CP_ASYNC16(sb + FS_SB0 + SMEM_SWIZZLE_128B((uint32_t)(r2 * 128 + u2 * 16)),
                       srcB + u);
        }
        CP_COMMIT();

        if (t < 64) rz1s[t] = g_rz1n[(b << 10) + (pt << 6) + t];
        #pragma unroll
        for (int k = 0; k < 2; k++) {
            int i = k * 512 + t;
            rz2s[i] = g_rz2n[(b << 10) + i];
            imgs[i] = make_float4(img[i], img[HWn + i], img[2 * HWn + i], 0.f);
        }
        // L2-prefetch this block's neg_idx slice
        const char* nh = (const char*)(neg_idx + ((size_t)(b * 2) << 18) + ((pt << 6) << 8));
        asm volatile("prefetch.global.L2 [%0];" :: "l"(nh + t * 128));
        asm volatile("prefetch.global.L2 [%0];" :: "l"(nh + (1 << 20) + t * 128));
        CP_WAIT0();
    }
    __syncthreads();

    // ---- hoist A fragments ----
    uint32_t af[4][2][4];
    #pragma unroll
    for (int ks = 0; ks < 4; ks++)
        #pragma unroll
        for (int mi = 0; mi < 2; mi++) {
            int row  = (wm << 5) + (mi << 4) + (lane & 15);
            int half = lane >> 4;
            uint32_t off = SMEM_SWIZZLE_128B((uint32_t)(row * 128 + ks * 32 + half * 16));
            ldsm_x4(af[ks][mi][0], af[ks][mi][1], af[ks][mi][2], af[ks][mi][3],
                    sb + FS_SA + off);
        }

    // ---- MMA mainloop over 8 q-tiles (cp.async double-buffered B) ----
    #pragma unroll 1
    for (int qt = 0; qt < 8; qt++) {
        const int cur = qt & 1;
        const uint32_t sbB = sb + (cur ? FS_SB1 : FS_SB0);

        if (qt < 7) {
            const uint32_t dstB = sb + ((cur ^ 1) ? FS_SB1 : FS_SB0);
            const uint4* srcB = (const uint4*)g_z2b +
                                (((size_t)(b << 10) + ((qt + 1) << 7)) << 3);
            #pragma unroll
            for (int k = 0; k < 2; k++) {
                int u = k * 512 + t;
                int r2 = u >> 3, u2 = u & 7;
                CP_ASYNC16(dstB + SMEM_SWIZZLE_128B((uint32_t)(r2 * 128 + u2 * 16)),
                           srcB + u);
            }
        }
        CP_COMMIT();

        float c[2][2][4];
        #pragma unroll
        for (int mi = 0; mi < 2; mi++)
            #pragma unroll
            for (int ni = 0; ni < 2; ni++)
                #pragma unroll
                for (int r = 0; r < 4; r++) c[mi][ni][r] = 0.f;

        #pragma unroll
        for (int ks = 0; ks < 4; ks++) {
            uint32_t bb[2][2];
            #pragma unroll
            for (int ni = 0; ni < 2; ni++) {
                int row  = (wn << 4) + (ni << 3) + (lane & 7);
                int half = (lane >> 3) & 1;
                uint32_t off = SMEM_SWIZZLE_128B((uint32_t)(row * 128 + ks * 32 + half * 16));
                ldsm_x2(bb[ni][0], bb[ni][1], sbB + off);
            }
            #pragma unroll
            for (int mi = 0; mi < 2; mi++)
                #pragma unroll
                for (int ni = 0; ni < 2; ni++)
                    mma16816(c[mi][ni], af[ks][mi], bb[ni]);
        }

        // epilogue: scale -> bf16x2 -> STS into SG
        #pragma unroll
        for (int mi = 0; mi < 2; mi++) {
            int r0 = (wm << 5) + (mi << 4) + (lane >> 2);
            int r1 = r0 + 8;
            float z1a = rz1s[r0], z1b = rz1s[r1];
            #pragma unroll
            for (int ni = 0; ni < 2; ni++) {
                int cq = (wn << 4) + (ni << 3) + ((lane & 3) << 1);
                int gq = (qt << 7) + cq;
                float rq0 = rz2s[gq], rq1 = rz2s[gq + 1];
                uint32_t u0, u1;
                float a0 = c[mi][ni][0] * z1a * rq0, a1 = c[mi][ni][1] * z1a * rq1;
                float b0 = c[mi][ni][2] * z1b * rq0, b1 = c[mi][ni][3] * z1b * rq1;
                asm("cvt.rn.bf16x2.f32 %0, %1, %2;" : "=r"(u0) : "f"(a1), "f"(a0));
                asm("cvt.rn.bf16x2.f32 %0, %1, %2;" : "=r"(u1) : "f"(b1), "f"(b0));
                *(uint32_t*)(smem + FS_SG + r0 * SG_PITCH + gq * 2) = u0;
                *(uint32_t*)(smem + FS_SG + r1 * SG_PITCH + gq * 2) = u1;
            }
        }
        CP_WAIT0();
        __syncthreads();
    }

    // ---- gather phase: int4 idx loads (4 LDG.128/p), pipelined; smem G-gather ----
    const float INV_EUC   = 1.0f / sqrtf((float)(31 * 31 + 31 * 31));
    const float INV_SQRT3 = 0.57735026919f;

    float acc[8];
    #pragma unroll
    for (int r = 0; r < 8; r++) acc[r] = 0.f;
    float sim0acc = 0.f;

    const int4* nH4 = (const int4*)(neg_idx + ((size_t)(b * 2) << 18));
    const int4* nW4 = nH4 + (1 << 16);          // (1<<18) ints = (1<<16) int4
    const int p0 = (pt << 6) + (w << 2);

    // prefetch it=0 q-indices: lane owns n = (r<<7) + (lane<<2) + e
    int qx[8];
    {
        const int4* h4 = nH4 + (p0 << 6);
        const int4* w4 = nW4 + (p0 << 6);
        #pragma unroll
        for (int r = 0; r < 2; r++) {
            int4 hv = h4[(r << 5) + lane];
            int4 wv = w4[(r << 5) + lane];
            qx[r * 4 + 0] = (hv.x << 5) + wv.x;
            qx[r * 4 + 1] = (hv.y << 5) + wv.y;
            qx[r * 4 + 2] = (hv.z << 5) + wv.z;
            qx[r * 4 + 3] = (hv.w << 5) + wv.w;
        }
    }

    #pragma unroll
    for (int it = 0; it < 4; it++) {
        int qc[8];
        #pragma unroll
        for (int r = 0; r < 8; r++) qc[r] = qx[r];

        if (it < 3) {   // prefetch next p's q-indices (overlaps compute below)
            const int4* h4 = nH4 + ((p0 + it + 1) << 6);
            const int4* w4 = nW4 + ((p0 + it + 1) << 6);
            #pragma unroll
            for (int r = 0; r < 2; r++) {
                int4 hv = h4[(r << 5) + lane];
                int4 wv = w4[(r << 5) + lane];
                qx[r * 4 + 0] = (hv.x << 5) + wv.x;
                qx[r * 4 + 1] = (hv.y << 5) + wv.y;
                qx[r * 4 + 2] = (hv.z << 5) + wv.z;
                qx[r * 4 + 3] = (hv.w << 5) + wv.w;
            }
        }

        const int pl = (w << 2) + it;
        const int p  = p0 + it;
        const float z1sqp = g_z1sq[(b << 10) + p];
        const float hp = (float)(p >> 5), wp = (float)(p & 31);
        const float4 ctr = imgs[p];

        float eucsq = 0.f, rgbsq = 0.f;
        #pragma unroll
        for (int r = 0; r < 8; r++) {
            int q  = qc[r];
            int nh = q >> 5, nw = q & 31;
            float dh = hp - (float)nh, dw = wp - (float)nw;
            eucsq += dh * dh; eucsq += dw * dw;
            float4 c4 = imgs[q];
            float dr = ctr.x - c4.x, dg = ctr.y - c4.y, db = ctr.z - c4.z;
            rgbsq += dr * dr; rgbsq += dg * dg; rgbsq += db * db;
        }
        #pragma unroll
        for (int s = 16; s > 0; s >>= 1) {
            eucsq += __shfl_xor_sync(0xffffffffu, eucsq, s);
            rgbsq += __shfl_xor_sync(0xffffffffu, rgbsq, s);
        }
        const float weight = 0.8f * sqrtf(eucsq) * INV_EUC
                           + 0.2f * sqrtf(rgbsq) * INV_SQRT3;

        const unsigned short* grow = (const unsigned short*)(smem + FS_SG + pl * SG_PITCH);
        #pragma unroll
        for (int r = 0; r < 8; r++) {
            float cosv = __uint_as_float((unsigned)grow[qc[r]] << 16);
            acc[r] += fminf(fabsf(cosv * weight), 1.0f);
        }
        if (lane == 0) {
            float c0 = z1sqp / fmaxf(z1sqp, 1e-8f);
            sim0acc += fminf(fabsf(c0), 1.0f);
        }
    }

    // store per-n sums: lane owns n = (r<<7)+(lane<<2)+e  ->  2x STS.128
    {
        float* dst = sdot + w * 256 + (lane << 2);
        *(float4*)dst         = make_float4(acc[0], acc[1], acc[2], acc[3]);
        *(float4*)(dst + 128) = make_float4(acc[4], acc[5], acc[6], acc[7]);
    }
    if (lane == 0) s0w[w] = sim0acc;
    __syncthreads();

    if (t < NEGn) {
        float s = 0.f;
        #pragma unroll
        for (int k = 0; k < 16; k++) s += sdot[k * 256 + t];
        g_pn[(((b << 4) + pt) << 8) + t] = s;
    }
    if (t == 0) {
        float s = 0.f;
        #pragma unroll
        for (int k = 0; k < 16; k++) s += s0w[k];
        g_s0p[(b << 4) + pt] = s;
    }

    // ---- last-block final reduction: fence on ONE thread only ----
    __syncthreads();
    if (t == 0) {
        __threadfence();
        *is_last = (atomicAdd(&g_ticket, 1u) == 127u);
    }
    __syncthreads();
    if (!*is_last) return;
    if (t == 0) {
        __threadfence();
        g_ticket = 0;
    }
    __syncthreads();

    {
        const int fb = t >> 6;
        const int j  = t & 63;

        float v1 = 0.f, v2 = 0.f;
        #pragma unroll
        for (int h = 0; h < 4; h++) {
            int n = j + (h << 6);
            float s = 0.f;
            #pragma unroll
            for (int k = 0; k < 16; k++)
                s += __ldcg(&g_pn[(((fb << 4) + k) << 8) + n]);
            float sn = s * (0.5f / 1024.0f);
            v2 += sn;
            v1 += fmaxf(log1pf(-sn), -100.0f);
        }
        #pragma unroll
        for (int s = 16; s > 0; s >>= 1) {
            v1 += __shfl_xor_sync(0xffffffffu, v1, s);
            v2 += __shfl_xor_sync(0xffffffffu, v2, s);
        }
        if (lane == 0) { r1s[w] = v1; r2s[w] = v2; }
        __syncthreads();

        if (t < 8) {
            float s1 = r1s[2 * t] + r1s[2 * t + 1];
            float s2 = r2s[2 * t] + r2s[2 * t + 1];
            float s0s = 0.f;
            #pragma unroll
            for (int k = 0; k < 16; k++) s0s += __ldcg(&g_s0p[(t << 4) + k]);
            float s0   = s0s * (1.0f / 1024.0f);
            float logp = fmaxf(logf(s0), -100.0f);
            lb[t]  = -(logp + s1) * (1.0f / 257.0f);
            s0b[t] = s0;
            s2b[t] = s2;
        }
        __syncthreads();

        if (t == 0) {
            float loss = 0.f, o1 = 0.f, o2 = 0.f;
            #pragma unroll
            for (int i = 0; i < 8; i++) { loss += lb[i]; o1 += s0b[i]; o2 += s2b[i]; }
            if (out_size > 0) out[0] = loss * 0.125f;
            if (out_size > 1) out[1] = o1 * 0.125f;
            if (out_size > 2) out[2] = o2 * (2.0f / (256.0f * 8.0f));
        }
    }
}

// ---------------- launch --------------------------------------------------------
extern "C" void kernel_launch(void* const* d_in, const int* in_sizes, int n_in,
                              void* d_out, int out_size) {
    const float* v1   = (const float*)d_in[0];
    const float* v2   = (const float*)d_in[1];
    const float* img  = (const float*)d_in[2];
    const int*   nidx = (const int*)  d_in[3];

    cudaFuncSetAttribute(fused_kernel, cudaFuncAttributeMaxDynamicSharedMemorySize,
                         FS_TOTAL);

    prep_kernel<<<dim3(8, 8, 2), 256>>>(v1, v2);
    fused_kernel<<<dim3(16, 8), 512, FS_TOTAL>>>(nidx, img, (float*)d_out, out_size);
}

// round 13
// speedup vs baseline: 1.2531x; 1.0770x over previous
#include <cuda_runtime.h>
#include <math.h>
#include <stdint.h>

#define Bn   8
#define HWn  1024
#define NEGn 256

// ---------------- device scratch ----------------------------------------------
__device__ __align__(16) unsigned g_z2b[Bn * HWn * 32];   // bf16x2 pixel-major, 128B rows
__device__ float g_rz2n[Bn * HWn];
__device__ float g_pn [128 * NEGn];
__device__ float g_s0p[128];
__device__ unsigned g_ticket = 0;
__device__ unsigned g_sync   = 0;

__device__ __forceinline__ uint32_t smem_to_u32(const void* p) {
    uint32_t a;
    asm("{ .reg .u64 t; cvta.to.shared.u64 t, %1; cvt.u32.u64 %0, t; }" : "=r"(a) : "l"(p));
    return a;
}
#define SMEM_SWIZZLE_128B(o) ((o) ^ (((o) >> 3) & 0x70))
#define CP_ASYNC16(dst_u32, src) \
    asm volatile("cp.async.cg.shared.global [%0], [%1], 16;" :: "r"(dst_u32), "l"(src))
#define CP_COMMIT() asm volatile("cp.async.commit_group;" ::: "memory")
#define CP_WAIT0()  asm volatile("cp.async.wait_group 0;" ::: "memory")

// round-to-nearest-even fp32 -> bf16-valued fp32
__device__ __forceinline__ float bf16q(float f) {
    unsigned u = __float_as_uint(f);
    u = (u + 0x7FFFu + ((u >> 16) & 1u)) & 0xFFFF0000u;
    return __uint_as_float(u);
}

__device__ __forceinline__ void ldsm_x4(uint32_t& r0, uint32_t& r1, uint32_t& r2,
                                        uint32_t& r3, uint32_t addr) {
    asm volatile("ldmatrix.sync.aligned.m8n8.x4.shared.b16 {%0,%1,%2,%3}, [%4];"
                 : "=r"(r0), "=r"(r1), "=r"(r2), "=r"(r3) : "r"(addr));
}
__device__ __forceinline__ void ldsm_x2(uint32_t& r0, uint32_t& r1, uint32_t addr) {
    asm volatile("ldmatrix.sync.aligned.m8n8.x2.shared.b16 {%0,%1}, [%2];"
                 : "=r"(r0), "=r"(r1) : "r"(addr));
}
__device__ __forceinline__ void mma16816(float* c, const uint32_t* a, const uint32_t* b) {
    asm volatile("mma.sync.aligned.m16n8k16.row.col.f32.bf16.bf16.f32 "
                 "{%0,%1,%2,%3}, {%4,%5,%6,%7}, {%8,%9}, {%0,%1,%2,%3};"
                 : "+f"(c[0]), "+f"(c[1]), "+f"(c[2]), "+f"(c[3])
                 : "r"(a[0]), "r"(a[1]), "r"(a[2]), "r"(a[3]), "r"(b[0]), "r"(b[1]));
}

// ---------------- single fused kernel: prep + grid-sync + GEMM + gather + final -
#define FS_SG    0
#define SG_PITCH 2064
#define FS_SB0   132096
#define FS_SB1   148480
#define FS_SA    164864
#define FS_RZ1   173056
#define FS_RZ2   173312
#define FS_IMG   177408
#define FS_DOT   193792
#define FS_MISC  210176
#define FS_TOTAL 210944
// prep staging (pre-MMA only; aliases SG region)
#define TS_PITCH 68

__global__ void __launch_bounds__(512) fused_kernel(
        const float* __restrict__ z1, const float* __restrict__ z2,
        const int* __restrict__ neg_idx, const float* __restrict__ img,
        float* __restrict__ out, int out_size) {
    extern __shared__ char smem[];
    const uint32_t sb = smem_to_u32(smem);
    const int t = threadIdx.x, w = t >> 5, lane = t & 31;
    const int pt = blockIdx.x, b = blockIdx.y;
    const int wm = w >> 3, wn = w & 7;

    float*  rz1s = (float*)(smem + FS_RZ1);
    float*  rz2s = (float*)(smem + FS_RZ2);
    float4* imgs = (float4*)(smem + FS_IMG);
    float*  sdot = (float*)(smem + FS_DOT);
    float*  s0w  = (float*)(smem + FS_MISC);
    float*  r1s  = (float*)(smem + FS_MISC + 64);
    float*  r2s  = (float*)(smem + FS_MISC + 128);
    float*  lb   = (float*)(smem + FS_MISC + 192);
    float*  s0b  = (float*)(smem + FS_MISC + 224);
    float*  s2b  = (float*)(smem + FS_MISC + 256);
    unsigned* is_last = (unsigned*)(smem + FS_MISC + 288);
    float*  z1sqs = (float*)(smem + FS_MISC + 320);   // 64 floats

    // ---- early: img table + neg_idx L2 prefetch (independent of prep/sync) ----
    {
        #pragma unroll
        for (int k = 0; k < 2; k++) {
            int i = k * 512 + t;
            imgs[i] = make_float4(img[i], img[HWn + i], img[2 * HWn + i], 0.f);
        }
        const char* nh = (const char*)(neg_idx + ((size_t)(b * 2) << 18) + ((pt << 6) << 8));
        asm volatile("prefetch.global.L2 [%0];" :: "l"(nh + t * 128));
        asm volatile("prefetch.global.L2 [%0];" :: "l"(nh + (1 << 20) + t * 128));
    }

    // ---- fused prep: stage z1 stripe + z2 share (two buffers, 2 syncs) ----
    {
        float* ts1 = (float*)(smem + FS_SG);            // 64 x 68 f32
        float* ts2 = (float*)(smem + FS_SG + 32768);
        const float* src1 = z1 + ((b * 64) << 10) + (pt << 6);
        const float* src2 = z2 + ((b * 64) << 10) + (pt << 6);

        #pragma unroll
        for (int k = 0; k < 2; k++) {
            int u = k * 512 + t;
            int c = u >> 4, j4 = (u & 15) * 4;          // 64 rows x 16 float4
            float4 v1 = *(const float4*)(src1 + (c << 10) + j4);
            float4 v2 = *(const float4*)(src2 + (c << 10) + j4);
            float* d1 = ts1 + c * TS_PITCH + j4;
            float* d2 = ts2 + c * TS_PITCH + j4;
            d1[0] = bf16q(v1.x); d1[1] = bf16q(v1.y);
            d1[2] = bf16q(v1.z); d1[3] = bf16q(v1.w);
            d2[0] = bf16q(v2.x); d2[1] = bf16q(v2.y);
            d2[2] = bf16q(v2.z); d2[3] = bf16q(v2.w);
        }
        __syncthreads();

        if (t < 64) {          // z1 norms (local only)
            float s = 0.f;
            #pragma unroll
            for (int c = 0; c < 64; c++) { float x = ts1[c * TS_PITCH + t]; s += x * x; }
            z1sqs[t] = s;
            rz1s[t]  = rsqrtf(s);
        } else if (t < 128) {  // z2 norms -> global
            int px = t - 64;
            float s = 0.f;
            #pragma unroll
            for (int c = 0; c < 64; c++) { float x = ts2[c * TS_PITCH + px]; s += x * x; }
            g_rz2n[(b << 10) + (pt << 6) + px] = rsqrtf(s);
        }

        // pack A tile (z1, swizzled smem) + z2 share (global, coalesced)
        #pragma unroll
        for (int k = 0; k < 4; k++) {
            int u = k * 512 + t;
            int px = u >> 5, cp = u & 31;
            unsigned lo1 = __float_as_uint(ts1[(2 * cp)     * TS_PITCH + px]) >> 16;
            unsigned hi1 = __float_as_uint(ts1[(2 * cp + 1) * TS_PITCH + px]) >> 16;
            *(uint32_t*)(smem + FS_SA + SMEM_SWIZZLE_128B((uint32_t)(px * 128 + cp * 4)))
                = lo1 | (hi1 << 16);
            unsigned lo2 = __float_as_uint(ts2[(2 * cp)     * TS_PITCH + px]) >> 16;
            unsigned hi2 = __float_as_uint(ts2[(2 * cp + 1) * TS_PITCH + px]) >> 16;
            g_z2b[(((b << 10) + (pt << 6) + px) << 5) + cp] = lo2 | (hi2 << 16);
        }
        __syncthreads();
    }

    // ---- software grid barrier (all 128 blocks co-resident: 1 block/SM) ----
    if (t == 0) {
        __threadfence();                        // release z2b / rz2n writes
        atomicAdd(&g_sync, 1u);
        unsigned v;
        do {
            asm volatile("ld.global.cg.u32 %0, [%1];" : "=r"(v) : "l"(&g_sync));
        } while (v < 128u);
        __threadfence();                        // acquire other blocks' writes
    }
    __syncthreads();

    // ---- prolog: B0 via cp.async, rz2n (L2) ----
    {
        const uint4* srcB = (const uint4*)g_z2b + ((size_t)(b << 10) << 3);
        #pragma unroll
        for (int k = 0; k < 2; k++) {
            int u = k * 512 + t;
            int r2 = u >> 3, u2 = u & 7;
            CP_ASYNC16(sb + FS_SB0 + SMEM_SWIZZLE_128B((uint32_t)(r2 * 128 + u2 * 16)),
                       srcB + u);
        }
        CP_COMMIT();
        #pragma unroll
        for (int k = 0; k < 2; k++) {
            int i = k * 512 + t;
            rz2s[i] = __ldcg(&g_rz2n[(b << 10) + i]);
        }
        CP_WAIT0();
    }
    __syncthreads();

    // ---- hoist A fragments ----
    uint32_t af[4][2][4];
    #pragma unroll
    for (int ks = 0; ks < 4; ks++)
        #pragma unroll
        for (int mi = 0; mi < 2; mi++) {
            int row  = (wm << 5) + (mi << 4) + (lane & 15);
            int half = lane >> 4;
            uint32_t off = SMEM_SWIZZLE_128B((uint32_t)(row * 128 + ks * 32 + half * 16));
            ldsm_x4(af[ks][mi][0], af[ks][mi][1], af[ks][mi][2], af[ks][mi][3],
                    sb + FS_SA + off);
        }

    // ---- MMA mainloop over 8 q-tiles (cp.async double-buffered B) ----
    #pragma unroll 1
    for (int qt = 0; qt < 8; qt++) {
        const int cur = qt & 1;
        const uint32_t sbB = sb + (cur ? FS_SB1 : FS_SB0);

        if (qt < 7) {
            const uint32_t dstB = sb + ((cur ^ 1) ? FS_SB1 : FS_SB0);
            const uint4* srcB = (const uint4*)g_z2b +
                                (((size_t)(b << 10) + ((qt + 1) << 7)) << 3);
            #pragma unroll
            for (int k = 0; k < 2; k++) {
                int u = k * 512 + t;
                int r2 = u >> 3, u2 = u & 7;
                CP_ASYNC16(dstB + SMEM_SWIZZLE_128B((uint32_t)(r2 * 128 + u2 * 16)),
                           srcB + u);
            }
        }
        CP_COMMIT();

        float c[2][2][4];
        #pragma unroll
        for (int mi = 0; mi < 2; mi++)
            #pragma unroll
            for (int ni = 0; ni < 2; ni++)
                #pragma unroll
                for (int r = 0; r < 4; r++) c[mi][ni][r] = 0.f;

        #pragma unroll
        for (int ks = 0; ks < 4; ks++) {
            uint32_t bb[2][2];
            #pragma unroll
            for (int ni = 0; ni < 2; ni++) {
                int row  = (wn << 4) + (ni << 3) + (lane & 7);
                int half = (lane >> 3) & 1;
                uint32_t off = SMEM_SWIZZLE_128B((uint32_t)(row * 128 + ks * 32 + half * 16));
                ldsm_x2(bb[ni][0], bb[ni][1], sbB + off);
            }
            #pragma unroll
            for (int mi = 0; mi < 2; mi++)
                #pragma unroll
                for (int ni = 0; ni < 2; ni++)
                    mma16816(c[mi][ni], af[ks][mi], bb[ni]);
        }

        // epilogue: scale -> bf16x2 -> STS into SG
        #pragma unroll
        for (int mi = 0; mi < 2; mi++) {
            int r0 = (wm << 5) + (mi << 4) + (lane >> 2);
            int r1 = r0 + 8;
            float z1a = rz1s[r0], z1b = rz1s[r1];
            #pragma unroll
            for (int ni = 0; ni < 2; ni++) {
                int cq = (wn << 4) + (ni << 3) + ((lane & 3) << 1);
                int gq = (qt << 7) + cq;
                float rq0 = rz2s[gq], rq1 = rz2s[gq + 1];
                uint32_t u0, u1;
                float a0 = c[mi][ni][0] * z1a * rq0, a1 = c[mi][ni][1] * z1a * rq1;
                float b0 = c[mi][ni][2] * z1b * rq0, b1 = c[mi][ni][3] * z1b * rq1;
                asm("cvt.rn.bf16x2.f32 %0, %1, %2;" : "=r"(u0) : "f"(a1), "f"(a0));
                asm("cvt.rn.bf16x2.f32 %0, %1, %2;" : "=r"(u1) : "f"(b1), "f"(b0));
                *(uint32_t*)(smem + FS_SG + r0 * SG_PITCH + gq * 2) = u0;
                *(uint32_t*)(smem + FS_SG + r1 * SG_PITCH + gq * 2) = u1;
            }
        }
        CP_WAIT0();
        __syncthreads();
    }

    // ---- gather phase: int4 idx loads, pipelined; smem G-gather ----
    const float INV_EUC   = 1.0f / sqrtf((float)(31 * 31 + 31 * 31));
    const float INV_SQRT3 = 0.57735026919f;

    float acc[8];
    #pragma unroll
    for (int r = 0; r < 8; r++) acc[r] = 0.f;
    float sim0acc = 0.f;

    const int4* nH4 = (const int4*)(neg_idx + ((size_t)(b * 2) << 18));
    const int4* nW4 = nH4 + (1 << 16);
    const int p0 = (pt << 6) + (w << 2);

    int qx[8];
    {
        const int4* h4 = nH4 + (p0 << 6);
        const int4* w4 = nW4 + (p0 << 6);
        #pragma unroll
        for (int r = 0; r < 2; r++) {
            int4 hv = h4[(r << 5) + lane];
            int4 wv = w4[(r << 5) + lane];
            qx[r * 4 + 0] = (hv.x << 5) + wv.x;
            qx[r * 4 + 1] = (hv.y << 5) + wv.y;
            qx[r * 4 + 2] = (hv.z << 5) + wv.z;
            qx[r * 4 + 3] = (hv.w << 5) + wv.w;
        }
    }

    #pragma unroll
    for (int it = 0; it < 4; it++) {
        int qc[8];
        #pragma unroll
        for (int r = 0; r < 8; r++) qc[r] = qx[r];

        if (it < 3) {
            const int4* h4 = nH4 + ((p0 + it + 1) << 6);
            const int4* w4 = nW4 + ((p0 + it + 1) << 6);
            #pragma unroll
            for (int r = 0; r < 2; r++) {
                int4 hv = h4[(r << 5) + lane];
                int4 wv = w4[(r << 5) + lane];
                qx[r * 4 + 0] = (hv.x << 5) + wv.x;
                qx[r * 4 + 1] = (hv.y << 5) + wv.y;
                qx[r * 4 + 2] = (hv.z << 5) + wv.z;
                qx[r * 4 + 3] = (hv.w << 5) + wv.w;
            }
        }

        const int pl = (w << 2) + it;
        const int p  = p0 + it;
        const float z1sqp = z1sqs[pl];
        const float hp = (float)(p >> 5), wp = (float)(p & 31);
        const float4 ctr = imgs[p];

        float eucsq = 0.f, rgbsq = 0.f;
        #pragma unroll
        for (int r = 0; r < 8; r++) {
            int q  = qc[r];
            int nh = q >> 5, nw = q & 31;
            float dh = hp - (float)nh, dw = wp - (float)nw;
            eucsq += dh * dh; eucsq += dw * dw;
            float4 c4 = imgs[q];
            float dr = ctr.x - c4.x, dg = ctr.y - c4.y, db = ctr.z - c4.z;
            rgbsq += dr * dr; rgbsq += dg * dg; rgbsq += db * db;
        }
        #pragma unroll
        for (int s = 16; s > 0; s >>= 1) {
            eucsq += __shfl_xor_sync(0xffffffffu, eucsq, s);
            rgbsq += __shfl_xor_sync(0xffffffffu, rgbsq, s);
        }
        const float weight = 0.8f * sqrtf(eucsq) * INV_EUC
                           + 0.2f * sqrtf(rgbsq) * INV_SQRT3;

        const unsigned short* grow = (const unsigned short*)(smem + FS_SG + pl * SG_PITCH);
        #pragma unroll
        for (int r = 0; r < 8; r++) {
            float cosv = __uint_as_float((unsigned)grow[qc[r]] << 16);
            acc[r] += fminf(fabsf(cosv * weight), 1.0f);
        }
        if (lane == 0) {
            float c0 = z1sqp / fmaxf(z1sqp, 1e-8f);
            sim0acc += fminf(fabsf(c0), 1.0f);
        }
    }

    // store per-n sums: lane owns n = (r<<7)+(lane<<2)+e  ->  2x STS.128
    {
        float* dst = sdot + w * 256 + (lane << 2);
        *(float4*)dst         = make_float4(acc[0], acc[1], acc[2], acc[3]);
        *(float4*)(dst + 128) = make_float4(acc[4], acc[5], acc[6], acc[7]);
    }
    if (lane == 0) s0w[w] = sim0acc;
    __syncthreads();

    if (t < NEGn) {
        float s = 0.f;
        #pragma unroll
        for (int k = 0; k < 16; k++) s += sdot[k * 256 + t];
        g_pn[(((b << 4) + pt) << 8) + t] = s;
    }
    if (t == 0) {
        float s = 0.f;
        #pragma unroll
        for (int k = 0; k < 16; k++) s += s0w[k];
        g_s0p[(b << 4) + pt] = s;
    }

    // ---- last-block final reduction: fence on ONE thread only ----
    __syncthreads();
    if (t == 0) {
        __threadfence();
        *is_last = (atomicAdd(&g_ticket, 1u) == 127u);
    }
    __syncthreads();
    if (!*is_last) return;
    if (t == 0) {
        __threadfence();
        g_ticket = 0;       // restore invariants for next graph replay
        g_sync   = 0;
    }
    __syncthreads();

    {
        const int fb = t >> 6;
        const int j  = t & 63;

        float v1 = 0.f, v2 = 0.f;
        #pragma unroll
        for (int h = 0; h < 4; h++) {
            int n = j + (h << 6);
            float s = 0.f;
            #pragma unroll
            for (int k = 0; k < 16; k++)
                s += __ldcg(&g_pn[(((fb << 4) + k) << 8) + n]);
            float sn = s * (0.5f / 1024.0f);
            v2 += sn;
            v1 += fmaxf(log1pf(-sn), -100.0f);
        }
        #pragma unroll
        for (int s = 16; s > 0; s >>= 1) {
            v1 += __shfl_xor_sync(0xffffffffu, v1, s);
            v2 += __shfl_xor_sync(0xffffffffu, v2, s);
        }
        if (lane == 0) { r1s[w] = v1; r2s[w] = v2; }
        __syncthreads();

        if (t < 8) {
            float s1 = r1s[2 * t] + r1s[2 * t + 1];
            float s2 = r2s[2 * t] + r2s[2 * t + 1];
            float s0s = 0.f;
            #pragma unroll
            for (int k = 0; k < 16; k++) s0s += __ldcg(&g_s0p[(t << 4) + k]);
            float s0   = s0s * (1.0f / 1024.0f);
            float logp = fmaxf(logf(s0), -100.0f);
            lb[t]  = -(logp + s1) * (1.0f / 257.0f);
            s0b[t] = s0;
            s2b[t] = s2;
        }
        __syncthreads();

        if (t == 0) {
            float loss = 0.f, o1 = 0.f, o2 = 0.f;
            #pragma unroll
            for (int i = 0; i < 8; i++) { loss += lb[i]; o1 += s0b[i]; o2 += s2b[i]; }
            if (out_size > 0) out[0] = loss * 0.125f;
            if (out_size > 1) out[1] = o1 * 0.125f;
            if (out_size > 2) out[2] = o2 * (2.0f / (256.0f * 8.0f));
        }
    }
}

// ---------------- launch --------------------------------------------------------
extern "C" void kernel_launch(void* const* d_in, const int* in_sizes, int n_in,
                              void* d_out, int out_size) {
    const float* v1   = (const float*)d_in[0];
    const float* v2   = (const float*)d_in[1];
    const float* img  = (const float*)d_in[2];
    const int*   nidx = (const int*)  d_in[3];

    cudaFuncSetAttribute(fused_kernel, cudaFuncAttributeMaxDynamicSharedMemorySize,
                         FS_TOTAL);

    fused_kernel<<<dim3(16, 8), 512, FS_TOTAL>>>(v1, v2, nidx, img,
                                                 (float*)d_out, out_size);
}

// round 14
// speedup vs baseline: 1.3908x; 1.1099x over previous
#include <cuda_runtime.h>
#include <math.h>
#include <stdint.h>

#define Bn   8
#define HWn  1024
#define NEGn 256

// ---------------- device scratch ----------------------------------------------
__device__ __align__(16) unsigned g_z2b[Bn * HWn * 32];   // bf16x2 pixel-major, 128B rows
__device__ float g_rz2n[Bn * HWn];
__device__ float g_pn [128 * NEGn];
__device__ float g_s0p[128];
__device__ unsigned g_ticket = 0;
__device__ unsigned g_sync   = 0;

__device__ __forceinline__ uint32_t smem_to_u32(const void* p) {
    uint32_t a;
    asm("{ .reg .u64 t; cvta.to.shared.u64 t, %1; cvt.u32.u64 %0, t; }" : "=r"(a) : "l"(p));
    return a;
}
#define SMEM_SWIZZLE_128B(o) ((o) ^ (((o) >> 3) & 0x70))
#define CP_ASYNC16(dst_u32, src) \
    asm volatile("cp.async.cg.shared.global [%0], [%1], 16;" :: "r"(dst_u32), "l"(src))
#define CP_COMMIT() asm volatile("cp.async.commit_group;" ::: "memory")
#define CP_WAIT0()  asm volatile("cp.async.wait_group 0;" ::: "memory")

// round-to-nearest-even fp32 -> bf16-valued fp32
__device__ __forceinline__ float bf16q(float f) {
    unsigned u = __float_as_uint(f);
    u = (u + 0x7FFFu + ((u >> 16) & 1u)) & 0xFFFF0000u;
    return __uint_as_float(u);
}

__device__ __forceinline__ void ldsm_x4(uint32_t& r0, uint32_t& r1, uint32_t& r2,
                                        uint32_t& r3, uint32_t addr) {
    asm volatile("ldmatrix.sync.aligned.m8n8.x4.shared.b16 {%0,%1,%2,%3}, [%4];"
                 : "=r"(r0), "=r"(r1), "=r"(r2), "=r"(r3) : "r"(addr));
}
__device__ __forceinline__ void ldsm_x2(uint32_t& r0, uint32_t& r1, uint32_t addr) {
    asm volatile("ldmatrix.sync.aligned.m8n8.x2.shared.b16 {%0,%1}, [%2];"
                 : "=r"(r0), "=r"(r1) : "r"(addr));
}
__device__ __forceinline__ void mma16816(float* c, const uint32_t* a, const uint32_t* b) {
    asm volatile("mma.sync.aligned.m16n8k16.row.col.f32.bf16.bf16.f32 "
                 "{%0,%1,%2,%3}, {%4,%5,%6,%7}, {%8,%9}, {%0,%1,%2,%3};"
                 : "+f"(c[0]), "+f"(c[1]), "+f"(c[2]), "+f"(c[3])
                 : "r"(a[0]), "r"(a[1]), "r"(a[2]), "r"(a[3]), "r"(b[0]), "r"(b[1]));
}

// ---------------- layout ---------------------------------------------------------
#define FS_SG    0
#define SG_PITCH 2064
#define FS_SB0   132096            // 256q B tile, 32 KB (sdot aliases this post-MMA)
#define FS_SB1   164864            // 32 KB
#define FS_SA    197632            // 8 KB
#define FS_RZ1   205824            // 64 f
#define FS_RZ2   206080            // 1024 f
#define FS_IMG   210176            // uint2[1024] = 8 KB (bf16 r,g,b packed)
#define FS_MISC  218368
#define FS_TOTAL 219136
#define TS_PITCH 68

__global__ void __launch_bounds__(512) fused_kernel(
        const float* __restrict__ z1, const float* __restrict__ z2,
        const int* __restrict__ neg_idx, const float* __restrict__ img,
        float* __restrict__ out, int out_size) {
    extern __shared__ char smem[];
    const uint32_t sb = smem_to_u32(smem);
    const int t = threadIdx.x, w = t >> 5, lane = t & 31;
    const int pt = blockIdx.x, b = blockIdx.y;
    const int wm = w >> 3, wn = w & 7;

    float*  rz1s = (float*)(smem + FS_RZ1);
    float*  rz2s = (float*)(smem + FS_RZ2);
    uint2*  imgs = (uint2*)(smem + FS_IMG);
    float*  sdot = (float*)(smem + FS_SB0);             // aliases B0 after MMA
    float*  s0w  = (float*)(smem + FS_MISC);
    float*  r1s  = (float*)(smem + FS_MISC + 64);
    float*  r2s  = (float*)(smem + FS_MISC + 128);
    float*  lb   = (float*)(smem + FS_MISC + 192);
    float*  s0b  = (float*)(smem + FS_MISC + 224);
    float*  s2b  = (float*)(smem + FS_MISC + 256);
    unsigned* is_last = (unsigned*)(smem + FS_MISC + 288);
    float*  z1sqs = (float*)(smem + FS_MISC + 320);     // 64 floats

    // ---- early: packed img table + neg_idx L2 prefetch ----
    {
        #pragma unroll
        for (int k = 0; k < 2; k++) {
            int i = k * 512 + t;
            unsigned r = __float_as_uint(bf16q(img[i])) >> 16;
            unsigned g = __float_as_uint(bf16q(img[HWn + i])) & 0xFFFF0000u;
            unsigned bc = __float_as_uint(bf16q(img[2 * HWn + i])) >> 16;
            imgs[i] = make_uint2(r | g, bc);
        }
        const char* nh = (const char*)(neg_idx + ((size_t)(b * 2) << 18) + ((pt << 6) << 8));
        asm volatile("prefetch.global.L2 [%0];" :: "l"(nh + t * 128));
        asm volatile("prefetch.global.L2 [%0];" :: "l"(nh + (1 << 20) + t * 128));
    }

    // ---- fused prep: stage z1 stripe + z2 share ----
    {
        float* ts1 = (float*)(smem + FS_SG);
        float* ts2 = (float*)(smem + FS_SG + 32768);
        const float* src1 = z1 + ((b * 64) << 10) + (pt << 6);
        const float* src2 = z2 + ((b * 64) << 10) + (pt << 6);

        #pragma unroll
        for (int k = 0; k < 2; k++) {
            int u = k * 512 + t;
            int c = u >> 4, j4 = (u & 15) * 4;
            float4 v1 = *(const float4*)(src1 + (c << 10) + j4);
            float4 v2 = *(const float4*)(src2 + (c << 10) + j4);
            float* d1 = ts1 + c * TS_PITCH + j4;
            float* d2 = ts2 + c * TS_PITCH + j4;
            d1[0] = bf16q(v1.x); d1[1] = bf16q(v1.y);
            d1[2] = bf16q(v1.z); d1[3] = bf16q(v1.w);
            d2[0] = bf16q(v2.x); d2[1] = bf16q(v2.y);
            d2[2] = bf16q(v2.z); d2[3] = bf16q(v2.w);
        }
        __syncthreads();

        if (t < 64) {
            float s = 0.f;
            #pragma unroll
            for (int c = 0; c < 64; c++) { float x = ts1[c * TS_PITCH + t]; s += x * x; }
            z1sqs[t] = s;
            rz1s[t]  = rsqrtf(s);
        } else if (t < 128) {
            int px = t - 64;
            float s = 0.f;
            #pragma unroll
            for (int c = 0; c < 64; c++) { float x = ts2[c * TS_PITCH + px]; s += x * x; }
            g_rz2n[(b << 10) + (pt << 6) + px] = rsqrtf(s);
        }

        #pragma unroll
        for (int k = 0; k < 4; k++) {
            int u = k * 512 + t;
            int px = u >> 5, cp = u & 31;
            unsigned lo1 = __float_as_uint(ts1[(2 * cp)     * TS_PITCH + px]) >> 16;
            unsigned hi1 = __float_as_uint(ts1[(2 * cp + 1) * TS_PITCH + px]) >> 16;
            *(uint32_t*)(smem + FS_SA + SMEM_SWIZZLE_128B((uint32_t)(px * 128 + cp * 4)))
                = lo1 | (hi1 << 16);
            unsigned lo2 = __float_as_uint(ts2[(2 * cp)     * TS_PITCH + px]) >> 16;
            unsigned hi2 = __float_as_uint(ts2[(2 * cp + 1) * TS_PITCH + px]) >> 16;
            g_z2b[(((b << 10) + (pt << 6) + px) << 5) + cp] = lo2 | (hi2 << 16);
        }
        __syncthreads();
    }

    // ---- software grid barrier (128 blocks co-resident) ----
    if (t == 0) {
        __threadfence();
        atomicAdd(&g_sync, 1u);
        unsigned v;
        do {
            asm volatile("ld.global.cg.u32 %0, [%1];" : "=r"(v) : "l"(&g_sync));
        } while (v < 128u);
        __threadfence();
    }
    __syncthreads();

    // ---- prolog: B0 (256 q rows) via cp.async, rz2n ----
    {
        const uint4* srcB = (const uint4*)g_z2b + ((size_t)(b << 10) << 3);
        #pragma unroll
        for (int k = 0; k < 4; k++) {
            int u = k * 512 + t;
            int r2 = u >> 3, u2 = u & 7;
            CP_ASYNC16(sb + FS_SB0 + SMEM_SWIZZLE_128B((uint32_t)(r2 * 128 + u2 * 16)),
                       srcB + u);
        }
        CP_COMMIT();
        #pragma unroll
        for (int k = 0; k < 2; k++) {
            int i = k * 512 + t;
            rz2s[i] = __ldcg(&g_rz2n[(b << 10) + i]);
        }
        CP_WAIT0();
    }
    __syncthreads();

    // ---- hoist A fragments ----
    uint32_t af[4][2][4];
    #pragma unroll
    for (int ks = 0; ks < 4; ks++)
        #pragma unroll
        for (int mi = 0; mi < 2; mi++) {
            int row  = (wm << 5) + (mi << 4) + (lane & 15);
            int half = lane >> 4;
            uint32_t off = SMEM_SWIZZLE_128B((uint32_t)(row * 128 + ks * 32 + half * 16));
            ldsm_x4(af[ks][mi][0], af[ks][mi][1], af[ks][mi][2], af[ks][mi][3],
                    sb + FS_SA + off);
        }

    // ---- MMA mainloop: 4 iterations of 256-q tiles (double-buffered) ----
    #pragma unroll 1
    for (int qt = 0; qt < 4; qt++) {
        const int cur = qt & 1;
        const uint32_t sbB = sb + (cur ? FS_SB1 : FS_SB0);

        if (qt < 3) {
            const uint32_t dstB = sb + ((cur ^ 1) ? FS_SB1 : FS_SB0);
            const uint4* srcB = (const uint4*)g_z2b +
                                (((size_t)(b << 10) + ((qt + 1) << 8)) << 3);
            #pragma unroll
            for (int k = 0; k < 4; k++) {
                int u = k * 512 + t;
                int r2 = u >> 3, u2 = u & 7;
                CP_ASYNC16(dstB + SMEM_SWIZZLE_128B((uint32_t)(r2 * 128 + u2 * 16)),
                           srcB + u);
            }
        }
        CP_COMMIT();

        float c[2][4][4];
        #pragma unroll
        for (int mi = 0; mi < 2; mi++)
            #pragma unroll
            for (int ni = 0; ni < 4; ni++)
                #pragma unroll
                for (int r = 0; r < 4; r++) c[mi][ni][r] = 0.f;

        #pragma unroll
        for (int ks = 0; ks < 4; ks++) {
            uint32_t bb[4][2];
            #pragma unroll
            for (int ni = 0; ni < 4; ni++) {
                int row  = (wn << 5) + (ni << 3) + (lane & 7);
                int half = (lane >> 3) & 1;
                uint32_t off = SMEM_SWIZZLE_128B((uint32_t)(row * 128 + ks * 32 + half * 16));
                ldsm_x2(bb[ni][0], bb[ni][1], sbB + off);
            }
            #pragma unroll
            for (int mi = 0; mi < 2; mi++)
                #pragma unroll
                for (int ni = 0; ni < 4; ni++)
                    mma16816(c[mi][ni], af[ks][mi], bb[ni]);
        }

        // epilogue: scale -> bf16x2 -> STS into SG
        #pragma unroll
        for (int mi = 0; mi < 2; mi++) {
            int r0 = (wm << 5) + (mi << 4) + (lane >> 2);
            int r1 = r0 + 8;
            float z1a = rz1s[r0], z1b = rz1s[r1];
            #pragma unroll
            for (int ni = 0; ni < 4; ni++) {
                int cq = (wn << 5) + (ni << 3) + ((lane & 3) << 1);
                int gq = (qt << 8) + cq;
                float rq0 = rz2s[gq], rq1 = rz2s[gq + 1];
                uint32_t u0, u1;
                float a0 = c[mi][ni][0] * z1a * rq0, a1 = c[mi][ni][1] * z1a * rq1;
                float b0 = c[mi][ni][2] * z1b * rq0, b1 = c[mi][ni][3] * z1b * rq1;
                asm("cvt.rn.bf16x2.f32 %0, %1, %2;" : "=r"(u0) : "f"(a1), "f"(a0));
                asm("cvt.rn.bf16x2.f32 %0, %1, %2;" : "=r"(u1) : "f"(b1), "f"(b0));
                *(uint32_t*)(smem + FS_SG + r0 * SG_PITCH + gq * 2) = u0;
                *(uint32_t*)(smem + FS_SG + r1 * SG_PITCH + gq * 2) = u1;
            }
        }
        CP_WAIT0();
        __syncthreads();
    }

    // ---- gather phase A: batched weights for 4 p's (interleaved chains) ----
    const float INV_EUC   = 1.0f / sqrtf((float)(31 * 31 + 31 * 31));
    const float INV_SQRT3 = 0.57735026919f;

    const int4* nH4 = (const int4*)(neg_idx + ((size_t)(b * 2) << 18));
    const int4* nW4 = nH4 + (1 << 16);
    const int p0 = (pt << 6) + (w << 2);

    int   qx[4][8];
    float esum[4], rsum[4];
    float sim0acc = 0.f;

    #pragma unroll
    for (int pi = 0; pi < 4; pi++) {
        const int p = p0 + pi;
        const int4* h4 = nH4 + (p << 6);
        const int4* w4 = nW4 + (p << 6);
        #pragma unroll
        for (int r = 0; r < 2; r++) {
            int4 hv = h4[(r << 5) + lane];
            int4 wv = w4[(r << 5) + lane];
            qx[pi][r * 4 + 0] = (hv.x << 5) + wv.x;
            qx[pi][r * 4 + 1] = (hv.y << 5) + wv.y;
            qx[pi][r * 4 + 2] = (hv.z << 5) + wv.z;
            qx[pi][r * 4 + 3] = (hv.w << 5) + wv.w;
        }

        const float hp = (float)(p >> 5), wp = (float)(p & 31);
        uint2 cu = imgs[p];
        float cr = __uint_as_float(cu.x << 16);
        float cg = __uint_as_float(cu.x & 0xFFFF0000u);
        float cb = __uint_as_float(cu.y << 16);

        float eucsq = 0.f, rgbsq = 0.f;
        #pragma unroll
        for (int r = 0; r < 8; r++) {
            int q  = qx[pi][r];
            int nh = q >> 5, nw = q & 31;
            float dh = hp - (float)nh, dw = wp - (float)nw;
            eucsq += dh * dh; eucsq += dw * dw;
            uint2 v = imgs[q];
            float dr = cr - __uint_as_float(v.x << 16);
            float dg = cg - __uint_as_float(v.x & 0xFFFF0000u);
            float db = cb - __uint_as_float(v.y << 16);
            rgbsq += dr * dr; rgbsq += dg * dg; rgbsq += db * db;
        }
        esum[pi] = eucsq; rsum[pi] = rgbsq;

        if (lane == 0) {
            float z1sqp = z1sqs[(w << 2) + pi];
            float c0 = z1sqp / fmaxf(z1sqp, 1e-8f);
            sim0acc += fminf(fabsf(c0), 1.0f);
        }
    }
    // 8 independent butterfly chains — overlap their latency
    #pragma unroll
    for (int s = 16; s > 0; s >>= 1) {
        #pragma unroll
        for (int pi = 0; pi < 4; pi++) {
            esum[pi] += __shfl_xor_sync(0xffffffffu, esum[pi], s);
            rsum[pi] += __shfl_xor_sync(0xffffffffu, rsum[pi], s);
        }
    }
    float wgt[4];
    #pragma unroll
    for (int pi = 0; pi < 4; pi++)
        wgt[pi] = 0.8f * sqrtf(esum[pi]) * INV_EUC + 0.2f * sqrtf(rsum[pi]) * INV_SQRT3;

    // ---- gather phase B: pure G-gathers ----
    float acc[8];
    #pragma unroll
    for (int r = 0; r < 8; r++) acc[r] = 0.f;

    #pragma unroll
    for (int pi = 0; pi < 4; pi++) {
        const unsigned short* grow =
            (const unsigned short*)(smem + FS_SG + ((w << 2) + pi) * SG_PITCH);
        const float wp = wgt[pi];
        #pragma unroll
        for (int r = 0; r < 8; r++) {
            float cosv = __uint_as_float((unsigned)grow[qx[pi][r]] << 16);
            acc[r] += fminf(fabsf(cosv * wp), 1.0f);
        }
    }

    // store per-n sums: lane owns n = (r<<7)+(lane<<2)+e  ->  2x STS.128
    __syncthreads();    // ensure all warps done reading SG/B0 before sdot alias writes
    {
        float* dst = sdot + w * 256 + (lane << 2);
        *(float4*)dst         = make_float4(acc[0], acc[1], acc[2], acc[3]);
        *(float4*)(dst + 128) = make_float4(acc[4], acc[5], acc[6], acc[7]);
    }
    if (lane == 0) s0w[w] = sim0acc;
    __syncthreads();

    if (t < NEGn) {
        float s = 0.f;
        #pragma unroll
        for (int k = 0; k < 16; k++) s += sdot[k * 256 + t];
        g_pn[(((b << 4) + pt) << 8) + t] = s;
    }
    if (t == 0) {
        float s = 0.f;
        #pragma unroll
        for (int k = 0; k < 16; k++) s += s0w[k];
        g_s0p[(b << 4) + pt] = s;
    }

    // ---- last-block final reduction ----
    __syncthreads();
    if (t == 0) {
        __threadfence();
        *is_last = (atomicAdd(&g_ticket, 1u) == 127u);
    }
    __syncthreads();
    if (!*is_last) return;
    if (t == 0) {
        __threadfence();
        g_ticket = 0;
        g_sync   = 0;
    }
    __syncthreads();

    {
        const int fb = t >> 6;
        const int j  = t & 63;

        float v1 = 0.f, v2 = 0.f;
        #pragma unroll
        for (int h = 0; h < 4; h++) {
            int n = j + (h << 6);
            float s = 0.f;
            #pragma unroll
            for (int k = 0; k < 16; k++)
                s += __ldcg(&g_pn[(((fb << 4) + k) << 8) + n]);
            float sn = s * (0.5f / 1024.0f);
            v2 += sn;
            v1 += fmaxf(log1pf(-sn), -100.0f);
        }
        #pragma unroll
        for (int s = 16; s > 0; s >>= 1) {
            v1 += __shfl_xor_sync(0xffffffffu, v1, s);
            v2 += __shfl_xor_sync(0xffffffffu, v2, s);
        }
        if (lane == 0) { r1s[w] = v1; r2s[w] = v2; }
        __syncthreads();

        if (t < 8) {
            float s1 = r1s[2 * t] + r1s[2 * t + 1];
            float s2 = r2s[2 * t] + r2s[2 * t + 1];
            float s0s = 0.f;
            #pragma unroll
            for (int k = 0; k < 16; k++) s0s += __ldcg(&g_s0p[(t << 4) + k]);
            float s0   = s0s * (1.0f / 1024.0f);
            float logp = fmaxf(logf(s0), -100.0f);
            lb[t]  = -(logp + s1) * (1.0f / 257.0f);
            s0b[t] = s0;
            s2b[t] = s2;
        }
        __syncthreads();

        if (t == 0) {
            float loss = 0.f, o1 = 0.f, o2 = 0.f;
            #pragma unroll
            for (int i = 0; i < 8; i++) { loss += lb[i]; o1 += s0b[i]; o2 += s2b[i]; }
            if (out_size > 0) out[0] = loss * 0.125f;
            if (out_size > 1) out[1] = o1 * 0.125f;
            if (out_size > 2) out[2] = o2 * (2.0f / (256.0f * 8.0f));
        }
    }
}

// ---------------- launch --------------------------------------------------------
extern "C" void kernel_launch(void* const* d_in, const int* in_sizes, int n_in,
                              void* d_out, int out_size) {
    const float* v1   = (const float*)d_in[0];
    const float* v2   = (const float*)d_in[1];
    const float* img  = (const float*)d_in[2];
    const int*   nidx = (const int*)  d_in[3];

    cudaFuncSetAttribute(fused_kernel, cudaFuncAttributeMaxDynamicSharedMemorySize,
                         FS_TOTAL);

    fused_kernel<<<dim3(16, 8), 512, FS_TOTAL>>>(v1, v2, nidx, img,
                                                 (float*)d_out, out_size);
}